// round 16
// baseline (speedup 1.0000x reference)
#include <cuda_runtime.h>
#include <cuda_bf16.h>

#define B_N   32768
#define M_N   8192
#define KNN   16
#define D_IN  66
#define EPSBN 1e-5f

// ---------------- scratch (no allocations allowed) ----------------
__device__ float4 g_mcn[M_N];                       // (mx, my, |m|^2, 0) all fp32
__device__ float  g_feat[(size_t)B_N * D_IN];       // knn features [B,66]
__device__ float  g_y1[(size_t)B_N * 128];
__device__ float  g_y2[(size_t)B_N * 256];
__device__ float  g_y3[(size_t)B_N * 512];
__device__ float  g_y4[(size_t)B_N * 128];
__device__ float  g_y5[(size_t)B_N * 64];
__device__ float  g_sum[5 * 512];
__device__ float  g_sq [5 * 512];
__device__ float  g_bna[5 * 512];                   // per-column scale
__device__ float  g_bnc[5 * 512];                   // per-column shift

// ---------------- prep: mc norms (separate roundings, CONFIRMED) ---------
__global__ void prep_kernel(const float2* __restrict__ mc) {
    int i = blockIdx.x * 256 + threadIdx.x;
    if (i < M_N) {
        float2 c = mc[i];
        float mn = __fadd_rn(__fmul_rn(c.x, c.x), __fmul_rn(c.y, c.y));
        g_mcn[i] = make_float4(c.x, c.y, mn, 0.f);
    }
    if (i < 5 * 512) { g_sum[i] = 0.f; g_sq[i] = 0.f; }
}

// ---------------- KNN: one thread per query point ----------------
// smem: float2 mc[8192] (64KB) + float mn[8192] (32KB) + stage 64*67 floats
#define KNN_SMEM (3 * M_N * 4 + 64 * 67 * 4)

__global__ __launch_bounds__(256) void knn_kernel(const float* __restrict__ pos,
                                                  const float* __restrict__ mv) {
    extern __shared__ float sh[];
    float2* smc   = (float2*)sh;            // [M_N]
    float*  smn   = sh + 2 * M_N;           // [M_N]
    float*  stage = sh + 3 * M_N;           // [64][67]

    for (int i = threadIdx.x; i < M_N; i += 256) {
        float4 v = g_mcn[i];
        smc[i] = make_float2(v.x, v.y);
        smn[i] = v.z;
    }
    __syncthreads();

    int p = blockIdx.x * 256 + threadIdx.x;
    float px = pos[2 * p], py = pos[2 * p + 1];
    // pn: separate roundings (CONFIRMED)
    float pn = __fadd_rn(__fmul_rn(px, px), __fmul_rn(py, py));

    float bd[KNN];
    int   bi[KNN];
#pragma unroll
    for (int i = 0; i < KNN; i++) { bd[i] = 3.4e38f; bi[i] = 0; }

#pragma unroll 4
    for (int j = 0; j < M_N; j++) {
        float2 m = smc[j];
        float  mn = smn[j];
        // asc-fma chain (CONFIRMED): dot = rn(py*my + rn(px*mx))
        float dot = fmaf(py, m.y, __fmul_rn(px, m.x));
        // assoc A (CONFIRMED): d2 = rn(rn(pn+mn) - 2*dot)
        float d2 = __fsub_rn(__fadd_rn(pn, mn), __fmul_rn(2.0f, dot));
        if (d2 < bd[KNN - 1]) {            // strict <: lo-index membership
            float cd = d2; int ci = j;
            bool  shl = false;             // SHIFT LATCH: once insertion
                                           // starts, shift unconditionally.
                                           // Per-slot compare alone stalls on
                                           // equal-valued runs (v < v false)
                                           // and silently swaps tie order —
                                           // the bug behind the 1.7e-2 floor.
#pragma unroll
            for (int t = 0; t < KNN; t++) {
                shl = shl || (cd < bd[t]);
                float od = bd[t]; int oi = bi[t];
                bd[t] = shl ? cd : od;  bi[t] = shl ? ci : oi;
                cd    = shl ? od : cd;  ci    = shl ? oi : ci;
            }
        }
    }

    // stage per-row features in smem (chunks of 64 rows), write coalesced
    for (int c = 0; c < 4; c++) {
        if ((threadIdx.x >> 6) == c) {
            int r = threadIdx.x & 63;
            float* row = stage + r * 67;
            row[0] = px; row[1] = py;
#pragma unroll
            for (int n = 0; n < KNN; n++) {
                int id = bi[n];
                float2 mcv = smc[id];
                float2 mvv = ((const float2*)mv)[id];
                row[2 + 4 * n] = mcv.x;
                row[3 + 4 * n] = mcv.y;
                row[4 + 4 * n] = mvv.x;
                row[5 + 4 * n] = mvv.y;
            }
        }
        __syncthreads();
        int rowBase = blockIdx.x * 256 + c * 64;
        for (int i = threadIdx.x; i < 64 * D_IN; i += 256) {
            int r = i / D_IN, cc = i - r * D_IN;
            g_feat[(size_t)(rowBase + r) * D_IN + cc] = stage[r * 67 + cc];
        }
        __syncthreads();
    }
}

// ---------------- fp32 SIMT GEMM, BM=BN=64, BK=16, 256 thr, 4x4/thr ----------
// PURE FP32 (tf32 experiment measured +1.28e-3 dense error -> reference is fp32)
// C[B,N] = act(A[B,K]) @ W[K,N] + bias; act = relu(a*x+c) if APPLY_BN.
// Epilogue accumulates per-column sum / sumsq (atomic, no-return).
template <bool APPLY_BN, bool STATS>
__global__ __launch_bounds__(256) void gemm_kernel(
    const float* __restrict__ A, const float* __restrict__ W,
    const float* __restrict__ bias, int Kdim, int Ndim,
    const float* __restrict__ bna, const float* __restrict__ bnc,
    float* __restrict__ C, float* __restrict__ sumP, float* __restrict__ sqP) {
    __shared__ float As[16][64];
    __shared__ float Bs[16][64];
    int tx = threadIdx.x & 15, ty = threadIdx.x >> 4;
    int rowBase = blockIdx.y * 64, colBase = blockIdx.x * 64;

    float acc[4][4] = {};

    for (int k0 = 0; k0 < Kdim; k0 += 16) {
        // A tile -> As[k][row]; fp32 BN+relu at load
        {
            int e = threadIdx.x * 4;
            int r = e >> 4, c0 = e & 15;
            const float* arow = A + (size_t)(rowBase + r) * Kdim + k0;
#pragma unroll
            for (int q = 0; q < 4; q++) {
                int c = c0 + q;
                float v = 0.f;
                if (k0 + c < Kdim) {
                    v = arow[c];
                    if (APPLY_BN) v = fmaxf(fmaf(bna[k0 + c], v, bnc[k0 + c]), 0.f);
                }
                As[c][r] = v;
            }
        }
        // W tile -> Bs[k][col]
        {
            int e = threadIdx.x * 4;
            int kk = e >> 6, c = e & 63;
            if (k0 + kk < Kdim) {
                float4 wv = *(const float4*)(W + (size_t)(k0 + kk) * Ndim + colBase + c);
                Bs[kk][c] = wv.x; Bs[kk][c + 1] = wv.y;
                Bs[kk][c + 2] = wv.z; Bs[kk][c + 3] = wv.w;
            } else {
                Bs[kk][c] = 0.f; Bs[kk][c + 1] = 0.f;
                Bs[kk][c + 2] = 0.f; Bs[kk][c + 3] = 0.f;
            }
        }
        __syncthreads();
#pragma unroll
        for (int kk = 0; kk < 16; kk++) {
            float4 av = *(const float4*)&As[kk][ty * 4];
            float4 bv = *(const float4*)&Bs[kk][tx * 4];
            float a[4] = {av.x, av.y, av.z, av.w};
            float b[4] = {bv.x, bv.y, bv.z, bv.w};
#pragma unroll
            for (int i = 0; i < 4; i++)
#pragma unroll
                for (int j = 0; j < 4; j++) acc[i][j] = fmaf(a[i], b[j], acc[i][j]);
        }
        __syncthreads();
    }

    // epilogue: +bias, write y (pre-BN), column stats
    int col0 = colBase + tx * 4;
    float bj[4];
#pragma unroll
    for (int j = 0; j < 4; j++) bj[j] = bias[col0 + j];
    float cs[4] = {}, cq[4] = {};
#pragma unroll
    for (int i = 0; i < 4; i++) {
        int row = rowBase + ty * 4 + i;
        float4 ov;
        float v0 = acc[i][0] + bj[0]; float v1 = acc[i][1] + bj[1];
        float v2 = acc[i][2] + bj[2]; float v3 = acc[i][3] + bj[3];
        ov.x = v0; ov.y = v1; ov.z = v2; ov.w = v3;
        cs[0] += v0; cs[1] += v1; cs[2] += v2; cs[3] += v3;
        cq[0] = fmaf(v0, v0, cq[0]); cq[1] = fmaf(v1, v1, cq[1]);
        cq[2] = fmaf(v2, v2, cq[2]); cq[3] = fmaf(v3, v3, cq[3]);
        *(float4*)(C + (size_t)row * Ndim + col0) = ov;
    }
    if (STATS) {
#pragma unroll
        for (int j = 0; j < 4; j++) {
            atomicAdd(&sumP[col0 + j], cs[j]);
            atomicAdd(&sqP[col0 + j], cq[j]);
        }
    }
}

// ---------------- per-layer BN params (a, c) ----------------
__global__ void bnparam_kernel(int L, int N, const float* __restrict__ g,
                               const float* __restrict__ be) {
    int i = blockIdx.x * 128 + threadIdx.x;
    if (i < N) {
        float s = g_sum[L * 512 + i], q = g_sq[L * 512 + i];
        float m = s * (1.0f / B_N);
        float v = fmaf(-m, m, q * (1.0f / B_N));
        v = fmaxf(v, 0.f);
        float a = g[i] * rsqrtf(v + EPSBN);
        g_bna[L * 512 + i] = a;
        g_bnc[L * 512 + i] = fmaf(-m, a, be[i]);
    }
}

// ---------------- final layer: BN5 + relu + [64x2] linear (fp32) ------------
__global__ __launch_bounds__(256) void final_kernel(const float* __restrict__ w6,
                                                    const float* __restrict__ b6,
                                                    float* __restrict__ out) {
    __shared__ float w0s[64], w1s[64], as[64], cs[64];
    if (threadIdx.x < 64) {
        w0s[threadIdx.x] = w6[threadIdx.x * 2];
        w1s[threadIdx.x] = w6[threadIdx.x * 2 + 1];
        as[threadIdx.x]  = g_bna[4 * 512 + threadIdx.x];
        cs[threadIdx.x]  = g_bnc[4 * 512 + threadIdx.x];
    }
    __syncthreads();
    int p = blockIdx.x * 256 + threadIdx.x;
    const float4* y = (const float4*)(g_y5 + (size_t)p * 64);
    float a0 = 0.f, a1 = 0.f;
#pragma unroll
    for (int k4 = 0; k4 < 16; k4++) {
        float4 yv = y[k4];
        float yy[4] = {yv.x, yv.y, yv.z, yv.w};
#pragma unroll
        for (int q = 0; q < 4; q++) {
            int k = k4 * 4 + q;
            float z = fmaxf(fmaf(as[k], yy[q], cs[k]), 0.f);
            a0 = fmaf(z, w0s[k], a0);
            a1 = fmaf(z, w1s[k], a1);
        }
    }
    out[2 * p]     = a0 + b6[0];
    out[2 * p + 1] = a1 + b6[1];
}

// ---------------- launch ----------------
extern "C" void kernel_launch(void* const* d_in, const int* in_sizes, int n_in,
                              void* d_out, int out_size) {
    const float* pos = (const float*)d_in[0];
    const float* mc  = (const float*)d_in[1];
    const float* mv  = (const float*)d_in[2];
    const float* w1 = (const float*)d_in[3];  const float* b1 = (const float*)d_in[4];
    const float* w2 = (const float*)d_in[5];  const float* b2 = (const float*)d_in[6];
    const float* w3 = (const float*)d_in[7];  const float* b3 = (const float*)d_in[8];
    const float* w4 = (const float*)d_in[9];  const float* b4 = (const float*)d_in[10];
    const float* w5 = (const float*)d_in[11]; const float* b5 = (const float*)d_in[12];
    const float* w6 = (const float*)d_in[13]; const float* b6 = (const float*)d_in[14];
    const float* g1 = (const float*)d_in[15]; const float* be1 = (const float*)d_in[16];
    const float* g2 = (const float*)d_in[17]; const float* be2 = (const float*)d_in[18];
    const float* g3 = (const float*)d_in[19]; const float* be3 = (const float*)d_in[20];
    const float* g4 = (const float*)d_in[21]; const float* be4 = (const float*)d_in[22];
    const float* g5 = (const float*)d_in[23]; const float* be5 = (const float*)d_in[24];

    float *p_feat, *p_y1, *p_y2, *p_y3, *p_y4, *p_y5, *p_sum, *p_sq, *p_bna, *p_bnc;
    cudaGetSymbolAddress((void**)&p_feat, g_feat);
    cudaGetSymbolAddress((void**)&p_y1, g_y1);
    cudaGetSymbolAddress((void**)&p_y2, g_y2);
    cudaGetSymbolAddress((void**)&p_y3, g_y3);
    cudaGetSymbolAddress((void**)&p_y4, g_y4);
    cudaGetSymbolAddress((void**)&p_y5, g_y5);
    cudaGetSymbolAddress((void**)&p_sum, g_sum);
    cudaGetSymbolAddress((void**)&p_sq, g_sq);
    cudaGetSymbolAddress((void**)&p_bna, g_bna);
    cudaGetSymbolAddress((void**)&p_bnc, g_bnc);

    cudaFuncSetAttribute(knn_kernel, cudaFuncAttributeMaxDynamicSharedMemorySize, KNN_SMEM);

    prep_kernel<<<32, 256>>>((const float2*)mc);
    knn_kernel<<<128, 256, KNN_SMEM>>>(pos, mv);

    // L1: 66 -> 128 (no BN on input)
    gemm_kernel<false, true><<<dim3(128 / 64, B_N / 64), 256>>>(
        p_feat, w1, b1, 66, 128, nullptr, nullptr, p_y1, p_sum + 0, p_sq + 0);
    bnparam_kernel<<<1, 128>>>(0, 128, g1, be1);
    // L2: 128 -> 256
    gemm_kernel<true, true><<<dim3(256 / 64, B_N / 64), 256>>>(
        p_y1, w2, b2, 128, 256, p_bna + 0, p_bnc + 0, p_y2, p_sum + 512, p_sq + 512);
    bnparam_kernel<<<2, 128>>>(1, 256, g2, be2);
    // L3: 256 -> 512
    gemm_kernel<true, true><<<dim3(512 / 64, B_N / 64), 256>>>(
        p_y2, w3, b3, 256, 512, p_bna + 512, p_bnc + 512, p_y3, p_sum + 1024, p_sq + 1024);
    bnparam_kernel<<<4, 128>>>(2, 512, g3, be3);
    // L4: 512 -> 128
    gemm_kernel<true, true><<<dim3(128 / 64, B_N / 64), 256>>>(
        p_y3, w4, b4, 512, 128, p_bna + 1024, p_bnc + 1024, p_y4, p_sum + 1536, p_sq + 1536);
    bnparam_kernel<<<1, 128>>>(3, 128, g4, be4);
    // L5: 128 -> 64
    gemm_kernel<true, true><<<dim3(64 / 64, B_N / 64), 256>>>(
        p_y4, w5, b5, 128, 64, p_bna + 1536, p_bnc + 1536, p_y5, p_sum + 2048, p_sq + 2048);
    bnparam_kernel<<<1, 128>>>(4, 64, g5, be5);
    // L6: 64 -> 2  (writes x to d_out[0 : 2B])
    final_kernel<<<B_N / 256, 256>>>(w6, b6, (float*)d_out);

    // second output: knn_feat right after x
    if (out_size >= (int)(B_N * (2 + D_IN))) {
        cudaMemcpyAsync((float*)d_out + 2 * B_N, p_feat,
                        (size_t)B_N * D_IN * sizeof(float),
                        cudaMemcpyDeviceToDevice);
    }
}